// round 2
// baseline (speedup 1.0000x reference)
#include <cuda_runtime.h>

// WindowAttention fused kernel: one CTA per window (4096 windows).
// x(64x256) -> QKV -> S=QK^T + phi/theta bias -> softmax -> P@V -> proj -> out
// All fp32 math via packed fma.rn.f32x2 (bit-identical to scalar fp32 FFMA).

#define NTOK 64
#define DIMC 256
#define XP   260   // padded row stride for Xs / A (Q,V)
#define KTP  64    // Kt row stride (Kt[d][j])
#define SSP  65    // P row stride
#define WTP  256   // W tile row stride

// smem layout (floats)
#define OFF_XS  0
#define OFF_A   16640      // 64*260
#define OFF_BT  33280      // + 64*260
#define OFF_SS  49664      // + 256*64
#define OFF_WT  53824      // + 64*65
#define OFF_TAB 57920      // + 16*256
#define SMEM_FLOATS 57984
#define SMEM_BYTES (SMEM_FLOATS * 4)

__device__ __forceinline__ unsigned long long pack2(float lo, float hi) {
    unsigned long long r;
    asm("mov.b64 %0, {%1, %2};" : "=l"(r) : "f"(lo), "f"(hi));
    return r;
}
__device__ __forceinline__ float2 unpack2(unsigned long long v) {
    float2 f;
    asm("mov.b64 {%0, %1}, %2;" : "=f"(f.x), "=f"(f.y) : "l"(v));
    return f;
}
__device__ __forceinline__ void ffma2(unsigned long long& d,
                                      unsigned long long a,
                                      unsigned long long b) {
    asm("fma.rn.f32x2 %0, %1, %2, %0;" : "+l"(d) : "l"(a), "l"(b));
}

// C(64x256) = Xin(64x256, row stride ldX) @ Wg(256x256 slice, row stride ldW)
// acc[rr][q*2+p] packs output cols (ct*4 + q*64 + 2p, +1) for row rt*4+rr.
__device__ __forceinline__ void gemm64x256(
    const float* __restrict__ Xin, int ldX,
    const float* __restrict__ Wg, int ldW,
    float* __restrict__ Wt, int tid,
    unsigned long long acc[4][8])
{
    const int ct = tid & 15;
    const int rt = tid >> 4;
#pragma unroll
    for (int rr = 0; rr < 4; ++rr)
#pragma unroll
        for (int qq = 0; qq < 8; ++qq) acc[rr][qq] = 0ull;

    for (int k0 = 0; k0 < 256; k0 += 16) {
        __syncthreads();
        // cooperative load of W tile [16][256]
#pragma unroll
        for (int i = 0; i < 4; ++i) {
            int e  = tid + 256 * i;        // float4 index, 0..1023
            int kk = e >> 6;
            int c4 = e & 63;
            *(float4*)&Wt[kk * WTP + c4 * 4] =
                *(const float4*)&Wg[(size_t)(k0 + kk) * ldW + c4 * 4];
        }
        __syncthreads();
#pragma unroll
        for (int kk = 0; kk < 16; ++kk) {
            unsigned long long xp[4];
#pragma unroll
            for (int rr = 0; rr < 4; ++rr) {
                float xv = Xin[(rt * 4 + rr) * ldX + k0 + kk];
                xp[rr] = pack2(xv, xv);
            }
#pragma unroll
            for (int q = 0; q < 4; ++q) {
                ulonglong2 wv = *(const ulonglong2*)&Wt[kk * WTP + ct * 4 + q * 64];
#pragma unroll
                for (int rr = 0; rr < 4; ++rr) {
                    ffma2(acc[rr][q * 2 + 0], xp[rr], wv.x);
                    ffma2(acc[rr][q * 2 + 1], xp[rr], wv.y);
                }
            }
        }
    }
}

__global__ void __launch_bounds__(256, 1)
win_attn_kernel(const float* __restrict__ x,
                const float* __restrict__ theta_max,
                const float* __restrict__ qkv_w,
                const float* __restrict__ qkv_b,
                const float* __restrict__ proj_w,
                const float* __restrict__ proj_b,
                const float* __restrict__ a_p,
                const float* __restrict__ b_p,
                const float* __restrict__ a_r,
                const float* __restrict__ b_r,
                float* __restrict__ out)
{
    extern __shared__ float sm[];
    float* Xs  = sm + OFF_XS;
    float* A   = sm + OFF_A;    // Q, then V
    float* Bt  = sm + OFF_BT;   // Kt[256][64], then O[64][256]
    float* Ss  = sm + OFF_SS;   // P[64][65]
    float* Wt  = sm + OFF_WT;
    float* tab = sm + OFF_TAB;  // a_p, b_p, a_r, b_r (16 floats apart)

    const int tid = threadIdx.x;
    const int w   = blockIdx.x;
    const float tm = __ldg(&theta_max[w >> 6]);

    if (tid < 15) {
        tab[tid]      = a_p[tid];
        tab[16 + tid] = b_p[tid];
        tab[32 + tid] = a_r[tid];
        tab[48 + tid] = b_r[tid];
    }

    // load x window into Xs (padded rows)
    const float4* xg = (const float4*)(x + (size_t)w * NTOK * DIMC);
#pragma unroll
    for (int i = 0; i < 16; ++i) {
        int e   = tid + 256 * i;   // 0..4095 float4s
        int row = e >> 6;
        int c4  = e & 63;
        *(float4*)&Xs[row * XP + c4 * 4] = xg[e];
    }

    const int ct = tid & 15;
    const int rt = tid >> 4;
    unsigned long long acc[4][8];

    // ---- Q = (Xs @ Wq + bq) * scale -> A ----
    gemm64x256(Xs, XP, qkv_w + 0, 768, Wt, tid, acc);
#pragma unroll
    for (int rr = 0; rr < 4; ++rr)
#pragma unroll
        for (int q = 0; q < 4; ++q)
#pragma unroll
            for (int p = 0; p < 2; ++p) {
                int c = ct * 4 + q * 64 + p * 2;
                int r = rt * 4 + rr;
                float2 v = unpack2(acc[rr][q * 2 + p]);
                v.x = (v.x + qkv_b[c])     * 0.0625f;
                v.y = (v.y + qkv_b[c + 1]) * 0.0625f;
                *(float2*)&A[r * XP + c] = v;
            }

    // ---- K = Xs @ Wk + bk -> Bt transposed: Bt[c][r] ----
    gemm64x256(Xs, XP, qkv_w + 256, 768, Wt, tid, acc);
#pragma unroll
    for (int rr = 0; rr < 4; ++rr)
#pragma unroll
        for (int q = 0; q < 4; ++q)
#pragma unroll
            for (int p = 0; p < 2; ++p) {
                int c = ct * 4 + q * 64 + p * 2;
                int r = rt * 4 + rr;
                float2 v = unpack2(acc[rr][q * 2 + p]);
                Bt[(c)     * KTP + r] = v.x + qkv_b[256 + c];
                Bt[(c + 1) * KTP + r] = v.y + qkv_b[256 + c + 1];
            }
    __syncthreads();

    // ---- S = Q @ K^T, add biases, softmax -> Ss ----
    {
        const int i  = tid >> 2;
        const int j0 = (tid & 3) * 16;
        unsigned long long sp[8];
#pragma unroll
        for (int p = 0; p < 8; ++p) sp[p] = 0ull;
        for (int d = 0; d < 256; ++d) {
            float qv = A[i * XP + d];
            unsigned long long qp = pack2(qv, qv);
#pragma unroll
            for (int e4 = 0; e4 < 4; ++e4) {
                ulonglong2 kv = *(const ulonglong2*)&Bt[d * KTP + j0 + e4 * 4];
                ffma2(sp[e4 * 2 + 0], qp, kv.x);
                ffma2(sp[e4 * 2 + 1], qp, kv.y);
            }
        }
        float s[16];
#pragma unroll
        for (int p = 0; p < 8; ++p) {
            float2 v = unpack2(sp[p]);
            s[2 * p] = v.x; s[2 * p + 1] = v.y;
        }
        const float C_AZ = 6.283185307179586f / 64.0f;   // 2*pi/W_RES
        const float tms  = tm * 0.015625f;               // tm / H_RES
        float mx = -1e30f;
#pragma unroll
        for (int jj = 0; jj < 16; ++jj) {
            int j  = j0 + jj;
            int dy = (i >> 3) - (j >> 3);   // radius
            int dx = (i & 7)  - (j & 7);    // azimuth
            int ai = (dx < 0) ? dx + 15 : dx;
            int ri = (dy < 0) ? dy + 15 : dy;
            float sph, cph, srn, crn;
            sincosf((float)dx * C_AZ, &sph, &cph);
            sincosf((float)dy * tms,  &srn, &crn);
            float bias = tab[ai] * cph + tab[16 + ai] * sph
                       + tab[32 + ri] * crn + tab[48 + ri] * srn;
            s[jj] += bias;
            mx = fmaxf(mx, s[jj]);
        }
        mx = fmaxf(mx, __shfl_xor_sync(0xffffffffu, mx, 1));
        mx = fmaxf(mx, __shfl_xor_sync(0xffffffffu, mx, 2));
        float sum = 0.0f;
#pragma unroll
        for (int jj = 0; jj < 16; ++jj) {
            s[jj] = expf(s[jj] - mx);
            sum += s[jj];
        }
        sum += __shfl_xor_sync(0xffffffffu, sum, 1);
        sum += __shfl_xor_sync(0xffffffffu, sum, 2);
        float inv = 1.0f / sum;
#pragma unroll
        for (int jj = 0; jj < 16; ++jj)
            Ss[i * SSP + j0 + jj] = s[jj] * inv;
    }
    // gemm's leading __syncthreads() orders Ss/Q reads before A (V) overwrite

    // ---- V = Xs @ Wv + bv -> A ----
    gemm64x256(Xs, XP, qkv_w + 512, 768, Wt, tid, acc);
#pragma unroll
    for (int rr = 0; rr < 4; ++rr)
#pragma unroll
        for (int q = 0; q < 4; ++q)
#pragma unroll
            for (int p = 0; p < 2; ++p) {
                int c = ct * 4 + q * 64 + p * 2;
                int r = rt * 4 + rr;
                float2 v = unpack2(acc[rr][q * 2 + p]);
                v.x += qkv_b[512 + c];
                v.y += qkv_b[512 + c + 1];
                *(float2*)&A[r * XP + c] = v;
            }
    __syncthreads();

    // ---- O = P @ V -> Bt[64][256] ----
    {
#pragma unroll
        for (int rr = 0; rr < 4; ++rr)
#pragma unroll
            for (int qq = 0; qq < 8; ++qq) acc[rr][qq] = 0ull;
#pragma unroll 8
        for (int j = 0; j < 64; ++j) {
            unsigned long long pp[4];
#pragma unroll
            for (int rr = 0; rr < 4; ++rr) {
                float pv = Ss[(rt * 4 + rr) * SSP + j];
                pp[rr] = pack2(pv, pv);
            }
#pragma unroll
            for (int q = 0; q < 4; ++q) {
                ulonglong2 vv = *(const ulonglong2*)&A[j * XP + ct * 4 + q * 64];
#pragma unroll
                for (int rr = 0; rr < 4; ++rr) {
                    ffma2(acc[rr][q * 2 + 0], pp[rr], vv.x);
                    ffma2(acc[rr][q * 2 + 1], pp[rr], vv.y);
                }
            }
        }
#pragma unroll
        for (int rr = 0; rr < 4; ++rr)
#pragma unroll
            for (int q = 0; q < 4; ++q)
#pragma unroll
                for (int p = 0; p < 2; ++p) {
                    int c = ct * 4 + q * 64 + p * 2;
                    int r = rt * 4 + rr;
                    *(float2*)&Bt[r * 256 + c] = unpack2(acc[rr][q * 2 + p]);
                }
    }
    // proj gemm's leading sync orders O writes before reads

    // ---- out = O @ proj_w + proj_b ----
    gemm64x256(Bt, 256, proj_w, 256, Wt, tid, acc);
    float* og = out + (size_t)w * NTOK * DIMC;
#pragma unroll
    for (int rr = 0; rr < 4; ++rr)
#pragma unroll
        for (int q = 0; q < 4; ++q)
#pragma unroll
            for (int p = 0; p < 2; ++p) {
                int c = ct * 4 + q * 64 + p * 2;
                int r = rt * 4 + rr;
                float2 v = unpack2(acc[rr][q * 2 + p]);
                v.x += proj_b[c];
                v.y += proj_b[c + 1];
                *(float2*)&og[r * 256 + c] = v;
            }
}

extern "C" void kernel_launch(void* const* d_in, const int* in_sizes, int n_in,
                              void* d_out, int out_size)
{
    (void)in_sizes; (void)n_in; (void)out_size;
    const float* x         = (const float*)d_in[0];
    const float* theta_max = (const float*)d_in[1];
    const float* qkv_w     = (const float*)d_in[2];
    const float* qkv_b     = (const float*)d_in[3];
    const float* proj_w    = (const float*)d_in[4];
    const float* proj_b    = (const float*)d_in[5];
    const float* a_p       = (const float*)d_in[6];
    const float* b_p       = (const float*)d_in[7];
    const float* a_r       = (const float*)d_in[8];
    const float* b_r       = (const float*)d_in[9];
    float* out = (float*)d_out;

    cudaFuncSetAttribute(win_attn_kernel,
                         cudaFuncAttributeMaxDynamicSharedMemorySize, SMEM_BYTES);
    win_attn_kernel<<<4096, 256, SMEM_BYTES>>>(
        x, theta_max, qkv_w, qkv_b, proj_w, proj_b,
        a_p, b_p, a_r, b_r, out);
}

// round 3
// speedup vs baseline: 1.0008x; 1.0008x over previous
#include <cuda_runtime.h>

// WindowAttention fused kernel: one CTA per window (4096 windows).
// x(64x256) -> QKV -> S=QK^T + phi/theta bias -> softmax -> P@V -> proj -> out
// All fp32 math via packed fma.rn.f32x2 (bit-identical to scalar fp32 FFMA).

#define NTOK 64
#define DIMC 256
#define XP   260   // padded row stride for Xs / A (Q,V)
#define KTP  64    // Kt row stride (Kt[d][j])
#define SSP  65    // P row stride
#define WTP  256   // W tile row stride

// smem layout (floats)
#define OFF_XS  0
#define OFF_A   16640      // 64*260
#define OFF_BT  33280      // + 64*260
#define OFF_SS  49664      // + 256*64
#define OFF_WT  53824      // + 64*65
#define OFF_TAB 57920      // + 16*256
#define SMEM_FLOATS 57984
#define SMEM_BYTES (SMEM_FLOATS * 4)

__device__ __forceinline__ unsigned long long pack2(float lo, float hi) {
    unsigned long long r;
    asm("mov.b64 %0, {%1, %2};" : "=l"(r) : "f"(lo), "f"(hi));
    return r;
}
__device__ __forceinline__ float2 unpack2(unsigned long long v) {
    float2 f;
    asm("mov.b64 {%0, %1}, %2;" : "=f"(f.x), "=f"(f.y) : "l"(v));
    return f;
}
__device__ __forceinline__ void ffma2(unsigned long long& d,
                                      unsigned long long a,
                                      unsigned long long b) {
    asm("fma.rn.f32x2 %0, %1, %2, %0;" : "+l"(d) : "l"(a), "l"(b));
}

// C(64x256) = Xin(64x256, row stride ldX) @ Wg(256x256 slice, row stride ldW)
// acc[rr][q*2+p] packs output cols (ct*4 + q*64 + 2p, +1) for row rt*4+rr.
__device__ __forceinline__ void gemm64x256(
    const float* __restrict__ Xin, int ldX,
    const float* __restrict__ Wg, int ldW,
    float* __restrict__ Wt, int tid,
    unsigned long long acc[4][8])
{
    const int ct = tid & 15;
    const int rt = tid >> 4;
#pragma unroll
    for (int rr = 0; rr < 4; ++rr)
#pragma unroll
        for (int qq = 0; qq < 8; ++qq) acc[rr][qq] = 0ull;

    for (int k0 = 0; k0 < 256; k0 += 16) {
        __syncthreads();
        // cooperative load of W tile [16][256]
#pragma unroll
        for (int i = 0; i < 4; ++i) {
            int e  = tid + 256 * i;        // float4 index, 0..1023
            int kk = e >> 6;
            int c4 = e & 63;
            *(float4*)&Wt[kk * WTP + c4 * 4] =
                *(const float4*)&Wg[(size_t)(k0 + kk) * ldW + c4 * 4];
        }
        __syncthreads();
#pragma unroll
        for (int kk = 0; kk < 16; ++kk) {
            unsigned long long xp[4];
#pragma unroll
            for (int rr = 0; rr < 4; ++rr) {
                float xv = Xin[(rt * 4 + rr) * ldX + k0 + kk];
                xp[rr] = pack2(xv, xv);
            }
#pragma unroll
            for (int q = 0; q < 4; ++q) {
                ulonglong2 wv = *(const ulonglong2*)&Wt[kk * WTP + ct * 4 + q * 64];
#pragma unroll
                for (int rr = 0; rr < 4; ++rr) {
                    ffma2(acc[rr][q * 2 + 0], xp[rr], wv.x);
                    ffma2(acc[rr][q * 2 + 1], xp[rr], wv.y);
                }
            }
        }
    }
}

__global__ void __launch_bounds__(256, 1)
win_attn_kernel(const float* __restrict__ x,
                const float* __restrict__ theta_max,
                const float* __restrict__ qkv_w,
                const float* __restrict__ qkv_b,
                const float* __restrict__ proj_w,
                const float* __restrict__ proj_b,
                const float* __restrict__ a_p,
                const float* __restrict__ b_p,
                const float* __restrict__ a_r,
                const float* __restrict__ b_r,
                float* __restrict__ out)
{
    extern __shared__ float sm[];
    float* Xs  = sm + OFF_XS;
    float* A   = sm + OFF_A;    // Q, then V
    float* Bt  = sm + OFF_BT;   // Kt[256][64], then O[64][256]
    float* Ss  = sm + OFF_SS;   // P[64][65]
    float* Wt  = sm + OFF_WT;
    float* tab = sm + OFF_TAB;  // a_p, b_p, a_r, b_r (16 floats apart)

    const int tid = threadIdx.x;
    const int w   = blockIdx.x;
    const float tm = __ldg(&theta_max[w >> 6]);

    if (tid < 15) {
        tab[tid]      = a_p[tid];
        tab[16 + tid] = b_p[tid];
        tab[32 + tid] = a_r[tid];
        tab[48 + tid] = b_r[tid];
    }

    // load x window into Xs (padded rows)
    const float4* xg = (const float4*)(x + (size_t)w * NTOK * DIMC);
#pragma unroll
    for (int i = 0; i < 16; ++i) {
        int e   = tid + 256 * i;   // 0..4095 float4s
        int row = e >> 6;
        int c4  = e & 63;
        *(float4*)&Xs[row * XP + c4 * 4] = xg[e];
    }

    const int ct = tid & 15;
    const int rt = tid >> 4;
    unsigned long long acc[4][8];

    // ---- Q = (Xs @ Wq + bq) * scale -> A ----
    gemm64x256(Xs, XP, qkv_w + 0, 768, Wt, tid, acc);
#pragma unroll
    for (int rr = 0; rr < 4; ++rr)
#pragma unroll
        for (int q = 0; q < 4; ++q)
#pragma unroll
            for (int p = 0; p < 2; ++p) {
                int c = ct * 4 + q * 64 + p * 2;
                int r = rt * 4 + rr;
                float2 v = unpack2(acc[rr][q * 2 + p]);
                v.x = (v.x + qkv_b[c])     * 0.0625f;
                v.y = (v.y + qkv_b[c + 1]) * 0.0625f;
                *(float2*)&A[r * XP + c] = v;
            }

    // ---- K = Xs @ Wk + bk -> Bt transposed: Bt[c][r] ----
    gemm64x256(Xs, XP, qkv_w + 256, 768, Wt, tid, acc);
#pragma unroll
    for (int rr = 0; rr < 4; ++rr)
#pragma unroll
        for (int q = 0; q < 4; ++q)
#pragma unroll
            for (int p = 0; p < 2; ++p) {
                int c = ct * 4 + q * 64 + p * 2;
                int r = rt * 4 + rr;
                float2 v = unpack2(acc[rr][q * 2 + p]);
                Bt[(c)     * KTP + r] = v.x + qkv_b[256 + c];
                Bt[(c + 1) * KTP + r] = v.y + qkv_b[256 + c + 1];
            }
    __syncthreads();

    // ---- S = Q @ K^T, add biases, softmax -> Ss ----
    {
        const int i  = tid >> 2;
        const int j0 = (tid & 3) * 16;
        unsigned long long sp[8];
#pragma unroll
        for (int p = 0; p < 8; ++p) sp[p] = 0ull;
        for (int d = 0; d < 256; ++d) {
            float qv = A[i * XP + d];
            unsigned long long qp = pack2(qv, qv);
#pragma unroll
            for (int e4 = 0; e4 < 4; ++e4) {
                ulonglong2 kv = *(const ulonglong2*)&Bt[d * KTP + j0 + e4 * 4];
                ffma2(sp[e4 * 2 + 0], qp, kv.x);
                ffma2(sp[e4 * 2 + 1], qp, kv.y);
            }
        }
        float s[16];
#pragma unroll
        for (int p = 0; p < 8; ++p) {
            float2 v = unpack2(sp[p]);
            s[2 * p] = v.x; s[2 * p + 1] = v.y;
        }
        const float C_AZ = 6.283185307179586f / 64.0f;   // 2*pi/W_RES
        const float tms  = tm * 0.015625f;               // tm / H_RES
        float mx = -1e30f;
#pragma unroll
        for (int jj = 0; jj < 16; ++jj) {
            int j  = j0 + jj;
            int dy = (i >> 3) - (j >> 3);   // radius
            int dx = (i & 7)  - (j & 7);    // azimuth
            int ai = (dx < 0) ? dx + 15 : dx;
            int ri = (dy < 0) ? dy + 15 : dy;
            float sph, cph, srn, crn;
            sincosf((float)dx * C_AZ, &sph, &cph);
            sincosf((float)dy * tms,  &srn, &crn);
            float bias = tab[ai] * cph + tab[16 + ai] * sph
                       + tab[32 + ri] * crn + tab[48 + ri] * srn;
            s[jj] += bias;
            mx = fmaxf(mx, s[jj]);
        }
        mx = fmaxf(mx, __shfl_xor_sync(0xffffffffu, mx, 1));
        mx = fmaxf(mx, __shfl_xor_sync(0xffffffffu, mx, 2));
        float sum = 0.0f;
#pragma unroll
        for (int jj = 0; jj < 16; ++jj) {
            s[jj] = expf(s[jj] - mx);
            sum += s[jj];
        }
        sum += __shfl_xor_sync(0xffffffffu, sum, 1);
        sum += __shfl_xor_sync(0xffffffffu, sum, 2);
        float inv = 1.0f / sum;
#pragma unroll
        for (int jj = 0; jj < 16; ++jj)
            Ss[i * SSP + j0 + jj] = s[jj] * inv;
    }
    // gemm's leading __syncthreads() orders Ss/Q reads before A (V) overwrite

    // ---- V = Xs @ Wv + bv -> A ----
    gemm64x256(Xs, XP, qkv_w + 512, 768, Wt, tid, acc);
#pragma unroll
    for (int rr = 0; rr < 4; ++rr)
#pragma unroll
        for (int q = 0; q < 4; ++q)
#pragma unroll
            for (int p = 0; p < 2; ++p) {
                int c = ct * 4 + q * 64 + p * 2;
                int r = rt * 4 + rr;
                float2 v = unpack2(acc[rr][q * 2 + p]);
                v.x += qkv_b[512 + c];
                v.y += qkv_b[512 + c + 1];
                *(float2*)&A[r * XP + c] = v;
            }
    __syncthreads();

    // ---- O = P @ V -> Bt[64][256] ----
    {
#pragma unroll
        for (int rr = 0; rr < 4; ++rr)
#pragma unroll
            for (int qq = 0; qq < 8; ++qq) acc[rr][qq] = 0ull;
#pragma unroll 8
        for (int j = 0; j < 64; ++j) {
            unsigned long long pp[4];
#pragma unroll
            for (int rr = 0; rr < 4; ++rr) {
                float pv = Ss[(rt * 4 + rr) * SSP + j];
                pp[rr] = pack2(pv, pv);
            }
#pragma unroll
            for (int q = 0; q < 4; ++q) {
                ulonglong2 vv = *(const ulonglong2*)&A[j * XP + ct * 4 + q * 64];
#pragma unroll
                for (int rr = 0; rr < 4; ++rr) {
                    ffma2(acc[rr][q * 2 + 0], pp[rr], vv.x);
                    ffma2(acc[rr][q * 2 + 1], pp[rr], vv.y);
                }
            }
        }
#pragma unroll
        for (int rr = 0; rr < 4; ++rr)
#pragma unroll
            for (int q = 0; q < 4; ++q)
#pragma unroll
                for (int p = 0; p < 2; ++p) {
                    int c = ct * 4 + q * 64 + p * 2;
                    int r = rt * 4 + rr;
                    *(float2*)&Bt[r * 256 + c] = unpack2(acc[rr][q * 2 + p]);
                }
    }
    // proj gemm's leading sync orders O writes before reads

    // ---- out = O @ proj_w + proj_b ----
    gemm64x256(Bt, 256, proj_w, 256, Wt, tid, acc);
    float* og = out + (size_t)w * NTOK * DIMC;
#pragma unroll
    for (int rr = 0; rr < 4; ++rr)
#pragma unroll
        for (int q = 0; q < 4; ++q)
#pragma unroll
            for (int p = 0; p < 2; ++p) {
                int c = ct * 4 + q * 64 + p * 2;
                int r = rt * 4 + rr;
                float2 v = unpack2(acc[rr][q * 2 + p]);
                v.x += proj_b[c];
                v.y += proj_b[c + 1];
                *(float2*)&og[r * 256 + c] = v;
            }
}

extern "C" void kernel_launch(void* const* d_in, const int* in_sizes, int n_in,
                              void* d_out, int out_size)
{
    (void)in_sizes; (void)n_in; (void)out_size;
    const float* x         = (const float*)d_in[0];
    const float* theta_max = (const float*)d_in[1];
    const float* qkv_w     = (const float*)d_in[2];
    const float* qkv_b     = (const float*)d_in[3];
    const float* proj_w    = (const float*)d_in[4];
    const float* proj_b    = (const float*)d_in[5];
    const float* a_p       = (const float*)d_in[6];
    const float* b_p       = (const float*)d_in[7];
    const float* a_r       = (const float*)d_in[8];
    const float* b_r       = (const float*)d_in[9];
    float* out = (float*)d_out;

    cudaFuncSetAttribute(win_attn_kernel,
                         cudaFuncAttributeMaxDynamicSharedMemorySize, SMEM_BYTES);
    win_attn_kernel<<<4096, 256, SMEM_BYTES>>>(
        x, theta_max, qkv_w, qkv_b, proj_w, proj_b,
        a_p, b_p, a_r, b_r, out);
}

// round 4
// speedup vs baseline: 1.0011x; 1.0003x over previous
#include <cuda_runtime.h>

// WindowAttention fused kernel: one CTA per window (4096 windows).
// x(64x256) -> QKV -> S=QK^T + phi/theta bias -> softmax -> P@V -> proj -> out
// All fp32 math via packed fma.rn.f32x2 (bit-identical to scalar fp32 FFMA).

#define NTOK 64
#define DIMC 256
#define XP   260   // padded row stride for Xs / A (Q,V)
#define KTP  64    // Kt row stride (Kt[d][j])
#define SSP  65    // P row stride
#define WTP  256   // W tile row stride

// smem layout (floats)
#define OFF_XS  0
#define OFF_A   16640      // 64*260
#define OFF_BT  33280      // + 64*260
#define OFF_SS  49664      // + 256*64
#define OFF_WT  53824      // + 64*65
#define OFF_TAB 57920      // + 16*256
#define SMEM_FLOATS 57984
#define SMEM_BYTES (SMEM_FLOATS * 4)

__device__ __forceinline__ unsigned long long pack2(float lo, float hi) {
    unsigned long long r;
    asm("mov.b64 %0, {%1, %2};" : "=l"(r) : "f"(lo), "f"(hi));
    return r;
}
__device__ __forceinline__ float2 unpack2(unsigned long long v) {
    float2 f;
    asm("mov.b64 {%0, %1}, %2;" : "=f"(f.x), "=f"(f.y) : "l"(v));
    return f;
}
__device__ __forceinline__ void ffma2(unsigned long long& d,
                                      unsigned long long a,
                                      unsigned long long b) {
    asm("fma.rn.f32x2 %0, %1, %2, %0;" : "+l"(d) : "l"(a), "l"(b));
}

// C(64x256) = Xin(64x256, row stride ldX) @ Wg(256x256 slice, row stride ldW)
// acc[rr][q*2+p] packs output cols (ct*4 + q*64 + 2p, +1) for row rt*4+rr.
__device__ __forceinline__ void gemm64x256(
    const float* __restrict__ Xin, int ldX,
    const float* __restrict__ Wg, int ldW,
    float* __restrict__ Wt, int tid,
    unsigned long long acc[4][8])
{
    const int ct = tid & 15;
    const int rt = tid >> 4;
#pragma unroll
    for (int rr = 0; rr < 4; ++rr)
#pragma unroll
        for (int qq = 0; qq < 8; ++qq) acc[rr][qq] = 0ull;

    for (int k0 = 0; k0 < 256; k0 += 16) {
        __syncthreads();
        // cooperative load of W tile [16][256]
#pragma unroll
        for (int i = 0; i < 4; ++i) {
            int e  = tid + 256 * i;        // float4 index, 0..1023
            int kk = e >> 6;
            int c4 = e & 63;
            *(float4*)&Wt[kk * WTP + c4 * 4] =
                *(const float4*)&Wg[(size_t)(k0 + kk) * ldW + c4 * 4];
        }
        __syncthreads();
#pragma unroll
        for (int kk = 0; kk < 16; ++kk) {
            unsigned long long xp[4];
#pragma unroll
            for (int rr = 0; rr < 4; ++rr) {
                float xv = Xin[(rt * 4 + rr) * ldX + k0 + kk];
                xp[rr] = pack2(xv, xv);
            }
#pragma unroll
            for (int q = 0; q < 4; ++q) {
                ulonglong2 wv = *(const ulonglong2*)&Wt[kk * WTP + ct * 4 + q * 64];
#pragma unroll
                for (int rr = 0; rr < 4; ++rr) {
                    ffma2(acc[rr][q * 2 + 0], xp[rr], wv.x);
                    ffma2(acc[rr][q * 2 + 1], xp[rr], wv.y);
                }
            }
        }
    }
}

__global__ void __launch_bounds__(256, 1)
win_attn_kernel(const float* __restrict__ x,
                const float* __restrict__ theta_max,
                const float* __restrict__ qkv_w,
                const float* __restrict__ qkv_b,
                const float* __restrict__ proj_w,
                const float* __restrict__ proj_b,
                const float* __restrict__ a_p,
                const float* __restrict__ b_p,
                const float* __restrict__ a_r,
                const float* __restrict__ b_r,
                float* __restrict__ out)
{
    extern __shared__ float sm[];
    float* Xs  = sm + OFF_XS;
    float* A   = sm + OFF_A;    // Q, then V
    float* Bt  = sm + OFF_BT;   // Kt[256][64], then O[64][256]
    float* Ss  = sm + OFF_SS;   // P[64][65]
    float* Wt  = sm + OFF_WT;
    float* tab = sm + OFF_TAB;  // a_p, b_p, a_r, b_r (16 floats apart)

    const int tid = threadIdx.x;
    const int w   = blockIdx.x;
    const float tm = __ldg(&theta_max[w >> 6]);

    if (tid < 15) {
        tab[tid]      = a_p[tid];
        tab[16 + tid] = b_p[tid];
        tab[32 + tid] = a_r[tid];
        tab[48 + tid] = b_r[tid];
    }

    // load x window into Xs (padded rows)
    const float4* xg = (const float4*)(x + (size_t)w * NTOK * DIMC);
#pragma unroll
    for (int i = 0; i < 16; ++i) {
        int e   = tid + 256 * i;   // 0..4095 float4s
        int row = e >> 6;
        int c4  = e & 63;
        *(float4*)&Xs[row * XP + c4 * 4] = xg[e];
    }

    const int ct = tid & 15;
    const int rt = tid >> 4;
    unsigned long long acc[4][8];

    // ---- Q = (Xs @ Wq + bq) * scale -> A ----
    gemm64x256(Xs, XP, qkv_w + 0, 768, Wt, tid, acc);
#pragma unroll
    for (int rr = 0; rr < 4; ++rr)
#pragma unroll
        for (int q = 0; q < 4; ++q)
#pragma unroll
            for (int p = 0; p < 2; ++p) {
                int c = ct * 4 + q * 64 + p * 2;
                int r = rt * 4 + rr;
                float2 v = unpack2(acc[rr][q * 2 + p]);
                v.x = (v.x + qkv_b[c])     * 0.0625f;
                v.y = (v.y + qkv_b[c + 1]) * 0.0625f;
                *(float2*)&A[r * XP + c] = v;
            }

    // ---- K = Xs @ Wk + bk -> Bt transposed: Bt[c][r] ----
    gemm64x256(Xs, XP, qkv_w + 256, 768, Wt, tid, acc);
#pragma unroll
    for (int rr = 0; rr < 4; ++rr)
#pragma unroll
        for (int q = 0; q < 4; ++q)
#pragma unroll
            for (int p = 0; p < 2; ++p) {
                int c = ct * 4 + q * 64 + p * 2;
                int r = rt * 4 + rr;
                float2 v = unpack2(acc[rr][q * 2 + p]);
                Bt[(c)     * KTP + r] = v.x + qkv_b[256 + c];
                Bt[(c + 1) * KTP + r] = v.y + qkv_b[256 + c + 1];
            }
    __syncthreads();

    // ---- S = Q @ K^T, add biases, softmax -> Ss ----
    {
        const int i  = tid >> 2;
        const int j0 = (tid & 3) * 16;
        unsigned long long sp[8];
#pragma unroll
        for (int p = 0; p < 8; ++p) sp[p] = 0ull;
        for (int d = 0; d < 256; ++d) {
            float qv = A[i * XP + d];
            unsigned long long qp = pack2(qv, qv);
#pragma unroll
            for (int e4 = 0; e4 < 4; ++e4) {
                ulonglong2 kv = *(const ulonglong2*)&Bt[d * KTP + j0 + e4 * 4];
                ffma2(sp[e4 * 2 + 0], qp, kv.x);
                ffma2(sp[e4 * 2 + 1], qp, kv.y);
            }
        }
        float s[16];
#pragma unroll
        for (int p = 0; p < 8; ++p) {
            float2 v = unpack2(sp[p]);
            s[2 * p] = v.x; s[2 * p + 1] = v.y;
        }
        const float C_AZ = 6.283185307179586f / 64.0f;   // 2*pi/W_RES
        const float tms  = tm * 0.015625f;               // tm / H_RES
        float mx = -1e30f;
#pragma unroll
        for (int jj = 0; jj < 16; ++jj) {
            int j  = j0 + jj;
            int dy = (i >> 3) - (j >> 3);   // radius
            int dx = (i & 7)  - (j & 7);    // azimuth
            int ai = (dx < 0) ? dx + 15 : dx;
            int ri = (dy < 0) ? dy + 15 : dy;
            float sph, cph, srn, crn;
            sincosf((float)dx * C_AZ, &sph, &cph);
            sincosf((float)dy * tms,  &srn, &crn);
            float bias = tab[ai] * cph + tab[16 + ai] * sph
                       + tab[32 + ri] * crn + tab[48 + ri] * srn;
            s[jj] += bias;
            mx = fmaxf(mx, s[jj]);
        }
        mx = fmaxf(mx, __shfl_xor_sync(0xffffffffu, mx, 1));
        mx = fmaxf(mx, __shfl_xor_sync(0xffffffffu, mx, 2));
        float sum = 0.0f;
#pragma unroll
        for (int jj = 0; jj < 16; ++jj) {
            s[jj] = expf(s[jj] - mx);
            sum += s[jj];
        }
        sum += __shfl_xor_sync(0xffffffffu, sum, 1);
        sum += __shfl_xor_sync(0xffffffffu, sum, 2);
        float inv = 1.0f / sum;
#pragma unroll
        for (int jj = 0; jj < 16; ++jj)
            Ss[i * SSP + j0 + jj] = s[jj] * inv;
    }
    // gemm's leading __syncthreads() orders Ss/Q reads before A (V) overwrite

    // ---- V = Xs @ Wv + bv -> A ----
    gemm64x256(Xs, XP, qkv_w + 512, 768, Wt, tid, acc);
#pragma unroll
    for (int rr = 0; rr < 4; ++rr)
#pragma unroll
        for (int q = 0; q < 4; ++q)
#pragma unroll
            for (int p = 0; p < 2; ++p) {
                int c = ct * 4 + q * 64 + p * 2;
                int r = rt * 4 + rr;
                float2 v = unpack2(acc[rr][q * 2 + p]);
                v.x += qkv_b[512 + c];
                v.y += qkv_b[512 + c + 1];
                *(float2*)&A[r * XP + c] = v;
            }
    __syncthreads();

    // ---- O = P @ V -> Bt[64][256] ----
    {
#pragma unroll
        for (int rr = 0; rr < 4; ++rr)
#pragma unroll
            for (int qq = 0; qq < 8; ++qq) acc[rr][qq] = 0ull;
#pragma unroll 8
        for (int j = 0; j < 64; ++j) {
            unsigned long long pp[4];
#pragma unroll
            for (int rr = 0; rr < 4; ++rr) {
                float pv = Ss[(rt * 4 + rr) * SSP + j];
                pp[rr] = pack2(pv, pv);
            }
#pragma unroll
            for (int q = 0; q < 4; ++q) {
                ulonglong2 vv = *(const ulonglong2*)&A[j * XP + ct * 4 + q * 64];
#pragma unroll
                for (int rr = 0; rr < 4; ++rr) {
                    ffma2(acc[rr][q * 2 + 0], pp[rr], vv.x);
                    ffma2(acc[rr][q * 2 + 1], pp[rr], vv.y);
                }
            }
        }
#pragma unroll
        for (int rr = 0; rr < 4; ++rr)
#pragma unroll
            for (int q = 0; q < 4; ++q)
#pragma unroll
                for (int p = 0; p < 2; ++p) {
                    int c = ct * 4 + q * 64 + p * 2;
                    int r = rt * 4 + rr;
                    *(float2*)&Bt[r * 256 + c] = unpack2(acc[rr][q * 2 + p]);
                }
    }
    // proj gemm's leading sync orders O writes before reads

    // ---- out = O @ proj_w + proj_b ----
    gemm64x256(Bt, 256, proj_w, 256, Wt, tid, acc);
    float* og = out + (size_t)w * NTOK * DIMC;
#pragma unroll
    for (int rr = 0; rr < 4; ++rr)
#pragma unroll
        for (int q = 0; q < 4; ++q)
#pragma unroll
            for (int p = 0; p < 2; ++p) {
                int c = ct * 4 + q * 64 + p * 2;
                int r = rt * 4 + rr;
                float2 v = unpack2(acc[rr][q * 2 + p]);
                v.x += proj_b[c];
                v.y += proj_b[c + 1];
                *(float2*)&og[r * 256 + c] = v;
            }
}

extern "C" void kernel_launch(void* const* d_in, const int* in_sizes, int n_in,
                              void* d_out, int out_size)
{
    (void)in_sizes; (void)n_in; (void)out_size;
    const float* x         = (const float*)d_in[0];
    const float* theta_max = (const float*)d_in[1];
    const float* qkv_w     = (const float*)d_in[2];
    const float* qkv_b     = (const float*)d_in[3];
    const float* proj_w    = (const float*)d_in[4];
    const float* proj_b    = (const float*)d_in[5];
    const float* a_p       = (const float*)d_in[6];
    const float* b_p       = (const float*)d_in[7];
    const float* a_r       = (const float*)d_in[8];
    const float* b_r       = (const float*)d_in[9];
    float* out = (float*)d_out;

    cudaFuncSetAttribute(win_attn_kernel,
                         cudaFuncAttributeMaxDynamicSharedMemorySize, SMEM_BYTES);
    win_attn_kernel<<<4096, 256, SMEM_BYTES>>>(
        x, theta_max, qkv_w, qkv_b, proj_w, proj_b,
        a_p, b_p, a_r, b_r, out);
}